// round 8
// baseline (speedup 1.0000x reference)
#include <cuda_runtime.h>
#include <cstdint>

// ---------------- problem constants ----------------
#define BB   256
#define CC   3
#define HH   224
#define WWD  224
#define RET  32
#define GDIM 9216          // 3 * 3 * 32 * 32
#define HGN  1024
#define HLN  256
#define HOUT 1280          // HG + HL

#define S1   24            // split-K for GEMM1 (K=9216 -> 384/split, 16 tiles of 24)
#define S2   8             // split-K for out GEMM (K=1024 -> 128/split)
#define S3   2             // split-K for hl GEMM  (K=256  -> 128/split)

#define BM   64
#define BN   128

// ---------------- scratch (device globals; no allocation allowed) ----------
__device__ float g_buf [BB * GDIM];          // foveated glimpse (B, 9216)
__device__ float h1_buf[BB * HGN];           // relu(g@W1+b1)
__device__ float h2_buf[BB * HLN];           // relu(loc@W2+b2)
__device__ float part1[S1 * BB * HGN];       // GEMM1 partials (24 MB)
__device__ float part2[S2 * BB * HOUT];      // h1@W3 partials
__device__ float part3[S3 * BB * HOUT];      // h2@W4 partials

// ---------------- packed fp32x2 helpers (sm_103a FFMA2) --------------------
__device__ __forceinline__ void fma2(unsigned long long& d,
                                     unsigned long long a,
                                     unsigned long long b) {
    asm("fma.rn.f32x2 %0, %1, %2, %0;" : "+l"(d) : "l"(a), "l"(b));
}
__device__ __forceinline__ unsigned long long pack_dup(float x) {
    unsigned long long r;
    unsigned xi = __float_as_uint(x);
    asm("mov.b64 %0, {%1, %2};" : "=l"(r) : "r"(xi), "r"(xi));
    return r;
}
__device__ __forceinline__ float2 unpack2(unsigned long long v) {
    unsigned lo, hi;
    asm("mov.b64 {%0, %1}, %2;" : "=r"(lo), "=r"(hi) : "l"(v));
    return make_float2(__uint_as_float(lo), __uint_as_float(hi));
}

// ---------------- cp.async helpers -----------------------------------------
__device__ __forceinline__ void cp16(uint32_t smem_dst, const void* gsrc) {
    asm volatile("cp.async.cg.shared.global [%0], [%1], 16;"
                 :: "r"(smem_dst), "l"(gsrc) : "memory");
}
__device__ __forceinline__ void cp_commit() {
    asm volatile("cp.async.commit_group;" ::: "memory");
}
template<int NG>
__device__ __forceinline__ void cp_wait() {
    asm volatile("cp.async.wait_group %0;" :: "n"(NG) : "memory");
}

// ---------------- foveation -----------------------------------------------
__global__ void foveate_kernel(const float* __restrict__ img,
                               const float* __restrict__ loc) {
    int idx = blockIdx.x * blockDim.x + threadIdx.x;
    if (idx >= BB * GDIM) return;
    int b  = idx / GDIM;
    int r  = idx - b * GDIM;
    int z  = r / (CC * RET * RET);
    int r2 = r - z * (CC * RET * RET);
    int c  = r2 / (RET * RET);
    int p  = r2 - c * (RET * RET);
    int y  = p >> 5;
    int x  = p & 31;

    float dr = (loc[b * 2 + 0] + 1.0f) * 0.5f * (float)WWD;
    float dc = (loc[b * 2 + 1] + 1.0f) * 0.5f * (float)WWD;
    int half = 16 << z;
    int top  = (int)(dr - (float)half);
    int left = (int)(dc - (float)half);

    const float* im = img + ((size_t)b * CC + c) * (HH * WWD);
    float v;
    if (z == 0) {
        v = im[(top + y) * WWD + (left + x)];
    } else {
        int off = (z == 2) ? 1 : 0;
        int yy = top  + (y << z) + off;
        int xx = left + (x << z) + off;
        const float* p0 = im + yy * WWD + xx;
        v = 0.25f * (p0[0] + p0[1] + p0[WWD] + p0[WWD + 1]);
    }
    g_buf[idx] = v;
}

// ---------------- location FC (K=2) ---------------------------------------
__global__ void loc_fc_kernel(const float* __restrict__ loc,
                              const float* __restrict__ W2,
                              const float* __restrict__ b2) {
    int b = blockIdx.x;
    int n = threadIdx.x;
    float l0 = loc[b * 2 + 0];
    float l1 = loc[b * 2 + 1];
    float v = fmaf(l0, W2[n], fmaf(l1, W2[HLN + n], b2[n]));
    h2_buf[b * HLN + n] = fmaxf(v, 0.0f);
}

// ---------------- split-K fp32 GEMM, cp.async double-buffered, FFMA2 -------
// part[z][M][N] = A[M x Kc chunk z] @ W[chunk z x N]
// BM=64, BN=128, BK=BKT, 128 threads, 8x8 per-thread tile.
// A row-major in smem; A consumed as float2 k-pairs (low live regs);
// accumulators packed over N pairs (W rows give natural u64 pairs).
template<int BKT, int MINB>
__global__ __launch_bounds__(128, MINB)
void gemm_splitk_kernel(const float* __restrict__ A, const float* __restrict__ W,
                        float* __restrict__ part, int M, int N, int K, int Kc) {
    __shared__ float As[2][BM][BKT];
    __shared__ float Ws[2][BKT][BN];

    const int tid = threadIdx.x;
    const int bm  = blockIdx.y;
    const int bn  = blockIdx.x;
    const int sz  = blockIdx.z;
    const int ty  = tid >> 4;       // 0..7  -> rows ty*8..+7
    const int tx  = tid & 15;       // 0..15 -> cols tx*8..+7

    const int kbase = sz * Kc;
    const int T     = Kc / BKT;

    const uint32_t as_base = (uint32_t)__cvta_generic_to_shared(&As[0][0][0]);
    const uint32_t ws_base = (uint32_t)__cvta_generic_to_shared(&Ws[0][0][0]);

    constexpr int ACH = BM * BKT / 512;   // A 16B-chunks per thread
    constexpr int WCH = BKT / 4;          // W 16B-chunks per thread
    constexpr int APR = BKT / 4;          // A float4 per row

    auto load_tiles = [&](int it, int b) {
        const int k0 = kbase + it * BKT;
        const float* Ag = A + (size_t)(bm * BM) * K + k0;
        #pragma unroll
        for (int t = 0; t < ACH; t++) {
            int id = t * 128 + tid;
            int m  = id / APR;
            int c  = (id % APR) << 2;
            cp16(as_base + (uint32_t)(((b * BM + m) * BKT + c) * 4),
                 Ag + (size_t)m * K + c);
        }
        const float* Wg = W + (size_t)k0 * N + bn * BN;
        #pragma unroll
        for (int t = 0; t < WCH; t++) {
            int id = t * 128 + tid;
            int kk = id >> 5;
            int nc = (id & 31) << 2;
            cp16(ws_base + (uint32_t)(((b * BKT + kk) * BN + nc) * 4),
                 Wg + (size_t)kk * N + nc);
        }
        cp_commit();
    };

    unsigned long long acc[8][4];   // [m-row][n-pair]
    #pragma unroll
    for (int i = 0; i < 8; i++)
        #pragma unroll
        for (int j = 0; j < 4; j++) acc[i][j] = 0ull;

    load_tiles(0, 0);

    int buf = 0;
    for (int it = 0; it < T; it++) {
        if (it + 1 < T) {
            load_tiles(it + 1, buf ^ 1);
            cp_wait<1>();
        } else {
            cp_wait<0>();
        }
        __syncthreads();

        const float (*Ab)[BKT] = As[buf];
        const float (*Wb)[BN]  = Ws[buf];

        #pragma unroll
        for (int kk4 = 0; kk4 < BKT; kk4 += 4) {
            #pragma unroll
            for (int jp = 0; jp < 2; jp++) {
                float2 av2[8];
                #pragma unroll
                for (int i = 0; i < 8; i++)
                    av2[i] = *(const float2*)(&Ab[ty * 8 + i][kk4 + jp * 2]);
                #pragma unroll
                for (int jj = 0; jj < 2; jj++) {
                    const ulonglong2* wp =
                        (const ulonglong2*)(&Wb[kk4 + jp * 2 + jj][tx * 8]);
                    ulonglong2 wA = wp[0];
                    ulonglong2 wB = wp[1];
                    #pragma unroll
                    for (int i = 0; i < 8; i++) {
                        float a = jj ? av2[i].y : av2[i].x;
                        unsigned long long ad = pack_dup(a);
                        fma2(acc[i][0], ad, wA.x);
                        fma2(acc[i][1], ad, wA.y);
                        fma2(acc[i][2], ad, wB.x);
                        fma2(acc[i][3], ad, wB.y);
                    }
                }
            }
        }
        __syncthreads();     // protect buf before it's refilled next iter
        buf ^= 1;
    }

    // write raw partials: part[sz][row][col]; acc pairs are (n, n+1)
    float* pout = part + (size_t)sz * M * N;
    const int col0 = bn * BN + tx * 8;
    #pragma unroll
    for (int i = 0; i < 8; i++) {
        int row = bm * BM + ty * 8 + i;
        float2 p0 = unpack2(acc[i][0]);
        float2 p1 = unpack2(acc[i][1]);
        float2 p2 = unpack2(acc[i][2]);
        float2 p3 = unpack2(acc[i][3]);
        *(float4*)(pout + (size_t)row * N + col0)     = make_float4(p0.x, p0.y, p1.x, p1.y);
        *(float4*)(pout + (size_t)row * N + col0 + 4) = make_float4(p2.x, p2.y, p3.x, p3.y);
    }
}

// ---------------- reduce 1: h1 = relu(sum_s part1 + b1) --------------------
__global__ void reduce1_kernel(const float* __restrict__ b1) {
    int idx4 = blockIdx.x * blockDim.x + threadIdx.x;        // over (BB*HGN)/4
    if (idx4 >= BB * HGN / 4) return;
    int idx = idx4 * 4;
    int n   = idx % HGN;
    float4 s = *(const float4*)(part1 + idx);
    #pragma unroll
    for (int z = 1; z < S1; z++) {
        float4 v = *(const float4*)(part1 + (size_t)z * BB * HGN + idx);
        s.x += v.x; s.y += v.y; s.z += v.z; s.w += v.w;
    }
    float4 bv = *(const float4*)(b1 + n);
    s.x = fmaxf(s.x + bv.x, 0.0f);
    s.y = fmaxf(s.y + bv.y, 0.0f);
    s.z = fmaxf(s.z + bv.z, 0.0f);
    s.w = fmaxf(s.w + bv.w, 0.0f);
    *(float4*)(h1_buf + idx) = s;
}

// ---------------- final reduce: out = relu(Σpart2+b3) + relu(Σpart3+b4) ----
__global__ void final_reduce_kernel(const float* __restrict__ b3,
                                    const float* __restrict__ b4,
                                    float* __restrict__ out) {
    int idx4 = blockIdx.x * blockDim.x + threadIdx.x;        // over (BB*HOUT)/4
    if (idx4 >= BB * HOUT / 4) return;
    int idx = idx4 * 4;
    int n   = idx % HOUT;

    float4 sg = *(const float4*)(part2 + idx);
    #pragma unroll
    for (int z = 1; z < S2; z++) {
        float4 v = *(const float4*)(part2 + (size_t)z * BB * HOUT + idx);
        sg.x += v.x; sg.y += v.y; sg.z += v.z; sg.w += v.w;
    }
    float4 sl = *(const float4*)(part3 + idx);
    #pragma unroll
    for (int z = 1; z < S3; z++) {
        float4 v = *(const float4*)(part3 + (size_t)z * BB * HOUT + idx);
        sl.x += v.x; sl.y += v.y; sl.z += v.z; sl.w += v.w;
    }
    float4 g3 = *(const float4*)(b3 + n);
    float4 g4 = *(const float4*)(b4 + n);
    float4 o;
    o.x = fmaxf(sg.x + g3.x, 0.0f) + fmaxf(sl.x + g4.x, 0.0f);
    o.y = fmaxf(sg.y + g3.y, 0.0f) + fmaxf(sl.y + g4.y, 0.0f);
    o.z = fmaxf(sg.z + g3.z, 0.0f) + fmaxf(sl.z + g4.z, 0.0f);
    o.w = fmaxf(sg.w + g3.w, 0.0f) + fmaxf(sl.w + g4.w, 0.0f);
    *(float4*)(out + idx) = o;        // relu(hg+hl) == relu(hg)+relu(hl)
}

// ---------------- launch ----------------------------------------------------
extern "C" void kernel_launch(void* const* d_in, const int* in_sizes, int n_in,
                              void* d_out, int out_size) {
    const float* images    = (const float*)d_in[0];
    const float* locations = (const float*)d_in[1];
    const float* W1        = (const float*)d_in[2];
    const float* b1        = (const float*)d_in[3];
    const float* W2        = (const float*)d_in[4];
    const float* b2        = (const float*)d_in[5];
    const float* W3        = (const float*)d_in[6];
    const float* b3        = (const float*)d_in[7];
    const float* W4        = (const float*)d_in[8];
    const float* b4        = (const float*)d_in[9];
    float* out = (float*)d_out;
    (void)in_sizes; (void)n_in; (void)out_size;

    void *gp, *h1p, *h2p, *p1p, *p2p, *p3p;
    cudaGetSymbolAddress(&gp,  g_buf);
    cudaGetSymbolAddress(&h1p, h1_buf);
    cudaGetSymbolAddress(&h2p, h2_buf);
    cudaGetSymbolAddress(&p1p, part1);
    cudaGetSymbolAddress(&p2p, part2);
    cudaGetSymbolAddress(&p3p, part3);

    // 1) foveation -> g_buf
    foveate_kernel<<<(BB * GDIM + 255) / 256, 256>>>(images, locations);

    // 2) location FC -> h2_buf
    loc_fc_kernel<<<BB, HLN>>>(locations, W2, b2);

    // 3) hl partials: h2 @ W4   (256 x 1280, K=256, S=2, BK=32) -> part3
    gemm_splitk_kernel<32, 4><<<dim3(HOUT / BN, BB / BM, S3), 128>>>(
        (const float*)h2p, W4, (float*)p3p, BB, HOUT, HLN, HLN / S3);

    // 4) GEMM1 partials: g @ W1 (256 x 1024, K=9216, S=24, BK=24) -> part1
    gemm_splitk_kernel<24, 5><<<dim3(HGN / BN, BB / BM, S1), 128>>>(
        (const float*)gp, W1, (float*)p1p, BB, HGN, GDIM, GDIM / S1);

    // 5) h1 = relu(sum part1 + b1)
    reduce1_kernel<<<(BB * HGN / 4 + 255) / 256, 256>>>(b1);

    // 6) out partials: h1 @ W3  (256 x 1280, K=1024, S=8, BK=32) -> part2
    gemm_splitk_kernel<32, 4><<<dim3(HOUT / BN, BB / BM, S2), 128>>>(
        (const float*)h1p, W3, (float*)p2p, BB, HOUT, HGN, HGN / S2);

    // 7) out = relu(sum part2 + b3) + relu(sum part3 + b4)
    final_reduce_kernel<<<(BB * HOUT / 4 + 255) / 256, 256>>>(b3, b4, out);
}

// round 9
// speedup vs baseline: 1.4550x; 1.4550x over previous
#include <cuda_runtime.h>
#include <cuda_bf16.h>
#include <cstdint>

// ---------------- problem constants ----------------
#define BB   256
#define CC   3
#define HH   224
#define WWD  224
#define RET  32
#define GDIM 9216          // 3 * 3 * 32 * 32
#define HGN  1024
#define HLN  256
#define HOUT 1280          // HG + HL

#define S1   9             // split-K GEMM1: 9216 -> Kc=1024 (32 tiles)
#define S2   8             // split-K out GEMM: 1024 -> Kc=128
#define S3   2             // split-K hl GEMM:  256 -> Kc=128

// ---------------- scratch (device globals; no allocation allowed) ----------
__device__ float g_buf [BB * GDIM];
__device__ float h1_buf[BB * HGN];
__device__ float h2_buf[BB * HLN];
__device__ float part1[S1 * BB * HGN];
__device__ float part2[S2 * BB * HOUT];
__device__ float part3[S3 * BB * HOUT];

// bf16 hi/lo split operands. A-side: [rows][K] row-major. B-side: [N][K] (transposed W).
__device__ __align__(16) __nv_bfloat16 g_h [BB * GDIM],  g_l [BB * GDIM];
__device__ __align__(16) __nv_bfloat16 h1_h[BB * HGN],   h1_l[BB * HGN];
__device__ __align__(16) __nv_bfloat16 h2_h[BB * HLN],   h2_l[BB * HLN];
__device__ __align__(16) __nv_bfloat16 w1_h[HGN * GDIM], w1_l[HGN * GDIM];   // [HGN][GDIM]
__device__ __align__(16) __nv_bfloat16 w3_h[HOUT * HGN], w3_l[HOUT * HGN];   // [HOUT][HGN]
__device__ __align__(16) __nv_bfloat16 w4_h[HOUT * HLN], w4_l[HOUT * HLN];   // [HOUT][HLN]

// ---------------- small PTX helpers ----------------------------------------
__device__ __forceinline__ void cp16(uint32_t smem_dst, const void* gsrc) {
    asm volatile("cp.async.cg.shared.global [%0], [%1], 16;"
                 :: "r"(smem_dst), "l"(gsrc) : "memory");
}
__device__ __forceinline__ void cp_commit() {
    asm volatile("cp.async.commit_group;" ::: "memory");
}
template<int NG>
__device__ __forceinline__ void cp_wait() {
    asm volatile("cp.async.wait_group %0;" :: "n"(NG) : "memory");
}
__device__ __forceinline__ void ldm_x4(uint32_t* r, uint32_t addr) {
    asm volatile("ldmatrix.sync.aligned.m8n8.x4.shared.b16 {%0,%1,%2,%3}, [%4];"
                 : "=r"(r[0]), "=r"(r[1]), "=r"(r[2]), "=r"(r[3]) : "r"(addr));
}
__device__ __forceinline__ void mma_bf16(float* c, const uint32_t* a, const uint32_t* b) {
    asm volatile("mma.sync.aligned.m16n8k16.row.col.f32.bf16.bf16.f32 "
                 "{%0,%1,%2,%3}, {%4,%5,%6,%7}, {%8,%9}, {%0,%1,%2,%3};"
                 : "+f"(c[0]), "+f"(c[1]), "+f"(c[2]), "+f"(c[3])
                 : "r"(a[0]), "r"(a[1]), "r"(a[2]), "r"(a[3]),
                   "r"(b[0]), "r"(b[1]));
}

// ---------------- foveation -----------------------------------------------
__global__ void foveate_kernel(const float* __restrict__ img,
                               const float* __restrict__ loc) {
    int idx = blockIdx.x * blockDim.x + threadIdx.x;
    if (idx >= BB * GDIM) return;
    int b  = idx / GDIM;
    int r  = idx - b * GDIM;
    int z  = r / (CC * RET * RET);
    int r2 = r - z * (CC * RET * RET);
    int c  = r2 / (RET * RET);
    int p  = r2 - c * (RET * RET);
    int y  = p >> 5;
    int x  = p & 31;

    float dr = (loc[b * 2 + 0] + 1.0f) * 0.5f * (float)WWD;
    float dc = (loc[b * 2 + 1] + 1.0f) * 0.5f * (float)WWD;
    int half = 16 << z;
    int top  = (int)(dr - (float)half);
    int left = (int)(dc - (float)half);

    const float* im = img + ((size_t)b * CC + c) * (HH * WWD);
    float v;
    if (z == 0) {
        v = im[(top + y) * WWD + (left + x)];
    } else {
        int off = (z == 2) ? 1 : 0;
        int yy = top  + (y << z) + off;
        int xx = left + (x << z) + off;
        const float* p0 = im + yy * WWD + xx;
        v = 0.25f * (p0[0] + p0[1] + p0[WWD] + p0[WWD + 1]);
    }
    g_buf[idx] = v;
}

// ---------------- location FC (K=2) ---------------------------------------
__global__ void loc_fc_kernel(const float* __restrict__ loc,
                              const float* __restrict__ W2,
                              const float* __restrict__ b2) {
    int b = blockIdx.x;
    int n = threadIdx.x;
    float l0 = loc[b * 2 + 0];
    float l1 = loc[b * 2 + 1];
    float v = fmaf(l0, W2[n], fmaf(l1, W2[HLN + n], b2[n]));
    h2_buf[b * HLN + n] = fmaxf(v, 0.0f);
}

// ---------------- fp32 -> bf16 hi/lo split (element-wise) ------------------
__global__ void conv_split_kernel(const float* __restrict__ in,
                                  __nv_bfloat16* __restrict__ oh,
                                  __nv_bfloat16* __restrict__ ol, int n2) {
    int i = blockIdx.x * 256 + threadIdx.x;
    if (i >= n2) return;
    float2 v = ((const float2*)in)[i];
    __nv_bfloat16 h0 = __float2bfloat16(v.x);
    __nv_bfloat16 h1 = __float2bfloat16(v.y);
    float r0 = v.x - __bfloat162float(h0);
    float r1 = v.y - __bfloat162float(h1);
    ((__nv_bfloat162*)oh)[i] = __halves2bfloat162(h0, h1);
    ((__nv_bfloat162*)ol)[i] = __halves2bfloat162(__float2bfloat16(r0),
                                                  __float2bfloat16(r1));
}

// ---------------- fp32 W[K][N] -> bf16 hi/lo transposed [N][K] -------------
__global__ void convT_split_kernel(const float* __restrict__ Win,
                                   __nv_bfloat16* __restrict__ oh,
                                   __nv_bfloat16* __restrict__ ol,
                                   int K, int N) {
    __shared__ float t[32][33];
    int k0 = blockIdx.y * 32, n0 = blockIdx.x * 32;
    int tx = threadIdx.x, ty = threadIdx.y;           // 32 x 8
    #pragma unroll
    for (int i = 0; i < 32; i += 8)
        t[ty + i][tx] = Win[(size_t)(k0 + ty + i) * N + n0 + tx];
    __syncthreads();
    #pragma unroll
    for (int i = 0; i < 32; i += 8) {
        int n = n0 + ty + i, k = k0 + tx;
        float x = t[tx][ty + i];
        __nv_bfloat16 h = __float2bfloat16(x);
        float r = x - __bfloat162float(h);
        oh[(size_t)n * K + k] = h;
        ol[(size_t)n * K + k] = __float2bfloat16(r);
    }
}

// ---------------- split-bf16 tensor-core split-K GEMM ----------------------
// part[z][M][N] = A[M x Kc chunk z] @ B^T  where A ~ Ah+Al, B(n,k) ~ Bh+Bl.
// 3-pass: Ah*Bh + Al*Bh + Ah*Bl (fp32 accumulate).  BM=BN=64, BK=32, 4 warps.
// smem rows padded to 40 bf16 (80 B) -> conflict-free ldmatrix (5 coprime 8).
__global__ __launch_bounds__(128, 4)
void mma_gemm_kernel(const __nv_bfloat16* __restrict__ Ah,
                     const __nv_bfloat16* __restrict__ Al,
                     const __nv_bfloat16* __restrict__ Bh,
                     const __nv_bfloat16* __restrict__ Bl,
                     float* __restrict__ part, int M, int N, int K, int Kc) {
    __shared__ __nv_bfloat16 sA[2][2][64][40];   // [stage][h/l][row][k]
    __shared__ __nv_bfloat16 sB[2][2][64][40];

    const int tid  = threadIdx.x;
    const int lane = tid & 31;
    const int warp = tid >> 5;
    const int bm   = blockIdx.y;
    const int bn   = blockIdx.x;
    const int sz   = blockIdx.z;
    const int kbase = sz * Kc;
    const int T     = Kc / 32;
    const int wm = (warp & 1) * 32;
    const int wn = (warp >> 1) * 32;

    const uint32_t sa0 = (uint32_t)__cvta_generic_to_shared(&sA[0][0][0][0]);
    const uint32_t sb0 = (uint32_t)__cvta_generic_to_shared(&sB[0][0][0][0]);
    // byte strides: stage=10240, h/l=5120, row=80

    auto load_stage = [&](int it, int s) {
        const int k0 = kbase + it * 32;
        #pragma unroll
        for (int t = 0; t < 2; t++) {
            int id = t * 128 + tid;
            int r  = id >> 2;            // 0..63
            int c  = (id & 3) * 8;       // 0,8,16,24 (bf16)
            uint32_t da = sa0 + (uint32_t)(s * 10240 + r * 80 + c * 2);
            uint32_t db = sb0 + (uint32_t)(s * 10240 + r * 80 + c * 2);
            size_t ga = (size_t)(bm * 64 + r) * K + k0 + c;
            size_t gb = (size_t)(bn * 64 + r) * K + k0 + c;
            cp16(da,        Ah + ga);
            cp16(da + 5120, Al + ga);
            cp16(db,        Bh + gb);
            cp16(db + 5120, Bl + gb);
        }
        cp_commit();
    };

    float acc[2][4][4] = {};

    // per-lane ldmatrix offsets (bytes, within a stage buffer)
    const uint32_t a_off  = (uint32_t)((wm + (lane & 15)) * 80 + ((lane >> 4) * 8) * 2);
    const uint32_t b_off0 = (uint32_t)((wn + (lane & 7) + ((lane >> 4) & 1) * 8) * 80
                                       + (((lane >> 3) & 1) * 8) * 2);
    const uint32_t b_off1 = b_off0 + 16 * 80;

    load_stage(0, 0);
    int buf = 0;
    for (int it = 0; it < T; it++) {
        if (it + 1 < T) { load_stage(it + 1, buf ^ 1); cp_wait<1>(); }
        else            { cp_wait<0>(); }
        __syncthreads();

        const uint32_t sa_s = sa0 + buf * 10240;
        const uint32_t sb_s = sb0 + buf * 10240;

        #pragma unroll
        for (int k16 = 0; k16 < 32; k16 += 16) {
            uint32_t aH[2][4], aL[2][4], bH[4][2], bL[4][2], tmp[4];
            #pragma unroll
            for (int mt = 0; mt < 2; mt++) {
                ldm_x4(aH[mt], sa_s        + a_off + mt * (16 * 80) + k16 * 2);
                ldm_x4(aL[mt], sa_s + 5120 + a_off + mt * (16 * 80) + k16 * 2);
            }
            #pragma unroll
            for (int nt2 = 0; nt2 < 2; nt2++) {
                uint32_t bo = nt2 ? b_off1 : b_off0;
                ldm_x4(tmp, sb_s + bo + k16 * 2);
                bH[nt2 * 2][0] = tmp[0]; bH[nt2 * 2][1] = tmp[1];
                bH[nt2 * 2 + 1][0] = tmp[2]; bH[nt2 * 2 + 1][1] = tmp[3];
                ldm_x4(tmp, sb_s + 5120 + bo + k16 * 2);
                bL[nt2 * 2][0] = tmp[0]; bL[nt2 * 2][1] = tmp[1];
                bL[nt2 * 2 + 1][0] = tmp[2]; bL[nt2 * 2 + 1][1] = tmp[3];
            }
            #pragma unroll
            for (int mt = 0; mt < 2; mt++)
                #pragma unroll
                for (int nt = 0; nt < 4; nt++) {
                    mma_bf16(acc[mt][nt], aH[mt], bH[nt]);
                    mma_bf16(acc[mt][nt], aL[mt], bH[nt]);
                    mma_bf16(acc[mt][nt], aH[mt], bL[nt]);
                }
        }
        __syncthreads();
        buf ^= 1;
    }

    // epilogue: raw partials
    float* pout = part + (size_t)sz * M * N;
    const int gm  = bm * 64 + wm + (lane >> 2);
    const int gn0 = bn * 64 + wn + (lane & 3) * 2;
    #pragma unroll
    for (int mt = 0; mt < 2; mt++)
        #pragma unroll
        for (int nt = 0; nt < 4; nt++) {
            int row = gm + mt * 16;
            int col = gn0 + nt * 8;
            *(float2*)&pout[(size_t)row * N + col] =
                make_float2(acc[mt][nt][0], acc[mt][nt][1]);
            *(float2*)&pout[(size_t)(row + 8) * N + col] =
                make_float2(acc[mt][nt][2], acc[mt][nt][3]);
        }
}

// ---------------- reduce 1: h1 = relu(sum_s part1 + b1) --------------------
__global__ void reduce1_kernel(const float* __restrict__ b1) {
    int idx4 = blockIdx.x * blockDim.x + threadIdx.x;
    if (idx4 >= BB * HGN / 4) return;
    int idx = idx4 * 4;
    int n   = idx % HGN;
    float4 s = *(const float4*)(part1 + idx);
    #pragma unroll
    for (int z = 1; z < S1; z++) {
        float4 v = *(const float4*)(part1 + (size_t)z * BB * HGN + idx);
        s.x += v.x; s.y += v.y; s.z += v.z; s.w += v.w;
    }
    float4 bv = *(const float4*)(b1 + n);
    s.x = fmaxf(s.x + bv.x, 0.0f);
    s.y = fmaxf(s.y + bv.y, 0.0f);
    s.z = fmaxf(s.z + bv.z, 0.0f);
    s.w = fmaxf(s.w + bv.w, 0.0f);
    *(float4*)(h1_buf + idx) = s;
}

// ---------------- final reduce: out = relu(Σpart2+b3) + relu(Σpart3+b4) ----
__global__ void final_reduce_kernel(const float* __restrict__ b3,
                                    const float* __restrict__ b4,
                                    float* __restrict__ out) {
    int idx4 = blockIdx.x * blockDim.x + threadIdx.x;
    if (idx4 >= BB * HOUT / 4) return;
    int idx = idx4 * 4;
    int n   = idx % HOUT;

    float4 sg = *(const float4*)(part2 + idx);
    #pragma unroll
    for (int z = 1; z < S2; z++) {
        float4 v = *(const float4*)(part2 + (size_t)z * BB * HOUT + idx);
        sg.x += v.x; sg.y += v.y; sg.z += v.z; sg.w += v.w;
    }
    float4 sl = *(const float4*)(part3 + idx);
    #pragma unroll
    for (int z = 1; z < S3; z++) {
        float4 v = *(const float4*)(part3 + (size_t)z * BB * HOUT + idx);
        sl.x += v.x; sl.y += v.y; sl.z += v.z; sl.w += v.w;
    }
    float4 g3 = *(const float4*)(b3 + n);
    float4 g4 = *(const float4*)(b4 + n);
    float4 o;
    o.x = fmaxf(sg.x + g3.x, 0.0f) + fmaxf(sl.x + g4.x, 0.0f);
    o.y = fmaxf(sg.y + g3.y, 0.0f) + fmaxf(sl.y + g4.y, 0.0f);
    o.z = fmaxf(sg.z + g3.z, 0.0f) + fmaxf(sl.z + g4.z, 0.0f);
    o.w = fmaxf(sg.w + g3.w, 0.0f) + fmaxf(sl.w + g4.w, 0.0f);
    *(float4*)(out + idx) = o;
}

// ---------------- launch ----------------------------------------------------
extern "C" void kernel_launch(void* const* d_in, const int* in_sizes, int n_in,
                              void* d_out, int out_size) {
    const float* images    = (const float*)d_in[0];
    const float* locations = (const float*)d_in[1];
    const float* W1        = (const float*)d_in[2];
    const float* b1        = (const float*)d_in[3];
    const float* W2        = (const float*)d_in[4];
    const float* b2        = (const float*)d_in[5];
    const float* W3        = (const float*)d_in[6];
    const float* b3        = (const float*)d_in[7];
    const float* W4        = (const float*)d_in[8];
    const float* b4        = (const float*)d_in[9];
    float* out = (float*)d_out;
    (void)in_sizes; (void)n_in; (void)out_size;

    void *gp, *h1p, *h2p, *p1p, *p2p, *p3p;
    void *ghp, *glp, *h1hp, *h1lp, *h2hp, *h2lp;
    void *w1hp, *w1lp, *w3hp, *w3lp, *w4hp, *w4lp;
    cudaGetSymbolAddress(&gp,   g_buf);
    cudaGetSymbolAddress(&h1p,  h1_buf);
    cudaGetSymbolAddress(&h2p,  h2_buf);
    cudaGetSymbolAddress(&p1p,  part1);
    cudaGetSymbolAddress(&p2p,  part2);
    cudaGetSymbolAddress(&p3p,  part3);
    cudaGetSymbolAddress(&ghp,  g_h);  cudaGetSymbolAddress(&glp,  g_l);
    cudaGetSymbolAddress(&h1hp, h1_h); cudaGetSymbolAddress(&h1lp, h1_l);
    cudaGetSymbolAddress(&h2hp, h2_h); cudaGetSymbolAddress(&h2lp, h2_l);
    cudaGetSymbolAddress(&w1hp, w1_h); cudaGetSymbolAddress(&w1lp, w1_l);
    cudaGetSymbolAddress(&w3hp, w3_h); cudaGetSymbolAddress(&w3lp, w3_l);
    cudaGetSymbolAddress(&w4hp, w4_h); cudaGetSymbolAddress(&w4lp, w4_l);

    // 1) foveation + location FC
    foveate_kernel<<<(BB * GDIM + 255) / 256, 256>>>(images, locations);
    loc_fc_kernel<<<BB, HLN>>>(locations, W2, b2);

    // 2) conversions (A-side splits + transposed W splits)
    conv_split_kernel<<<(BB * GDIM / 2 + 255) / 256, 256>>>(
        (const float*)gp, (__nv_bfloat16*)ghp, (__nv_bfloat16*)glp, BB * GDIM / 2);
    conv_split_kernel<<<(BB * HLN / 2 + 255) / 256, 256>>>(
        (const float*)h2p, (__nv_bfloat16*)h2hp, (__nv_bfloat16*)h2lp, BB * HLN / 2);
    convT_split_kernel<<<dim3(HGN / 32, GDIM / 32), dim3(32, 8)>>>(
        W1, (__nv_bfloat16*)w1hp, (__nv_bfloat16*)w1lp, GDIM, HGN);
    convT_split_kernel<<<dim3(HOUT / 32, HLN / 32), dim3(32, 8)>>>(
        W4, (__nv_bfloat16*)w4hp, (__nv_bfloat16*)w4lp, HLN, HOUT);
    convT_split_kernel<<<dim3(HOUT / 32, HGN / 32), dim3(32, 8)>>>(
        W3, (__nv_bfloat16*)w3hp, (__nv_bfloat16*)w3lp, HGN, HOUT);

    // 3) hl partials: h2 @ W4^T  (M=256, N=1280, K=256, S=2)
    mma_gemm_kernel<<<dim3(HOUT / 64, BB / 64, S3), 128>>>(
        (const __nv_bfloat16*)h2hp, (const __nv_bfloat16*)h2lp,
        (const __nv_bfloat16*)w4hp, (const __nv_bfloat16*)w4lp,
        (float*)p3p, BB, HOUT, HLN, HLN / S3);

    // 4) GEMM1 partials: g @ W1^T (M=256, N=1024, K=9216, S=9)
    mma_gemm_kernel<<<dim3(HGN / 64, BB / 64, S1), 128>>>(
        (const __nv_bfloat16*)ghp, (const __nv_bfloat16*)glp,
        (const __nv_bfloat16*)w1hp, (const __nv_bfloat16*)w1lp,
        (float*)p1p, BB, HGN, GDIM, GDIM / S1);

    // 5) h1 = relu(sum part1 + b1), then split to bf16
    reduce1_kernel<<<(BB * HGN / 4 + 255) / 256, 256>>>(b1);
    conv_split_kernel<<<(BB * HGN / 2 + 255) / 256, 256>>>(
        (const float*)h1p, (__nv_bfloat16*)h1hp, (__nv_bfloat16*)h1lp, BB * HGN / 2);

    // 6) out partials: h1 @ W3^T (M=256, N=1280, K=1024, S=8)
    mma_gemm_kernel<<<dim3(HOUT / 64, BB / 64, S2), 128>>>(
        (const __nv_bfloat16*)h1hp, (const __nv_bfloat16*)h1lp,
        (const __nv_bfloat16*)w3hp, (const __nv_bfloat16*)w3lp,
        (float*)p2p, BB, HOUT, HGN, HGN / S2);

    // 7) out = relu(sum part2 + b3) + relu(sum part3 + b4)
    final_reduce_kernel<<<(BB * HOUT / 4 + 255) / 256, 256>>>(b3, b4, out);
}

// round 10
// speedup vs baseline: 2.1924x; 1.5069x over previous
#include <cuda_runtime.h>
#include <cuda_bf16.h>
#include <cstdint>

// ---------------- problem constants ----------------
#define BB   256
#define CC   3
#define HH   224
#define WWD  224
#define RET  32
#define GDIM 9216          // 3 * 3 * 32 * 32
#define HGN  1024
#define HLN  256
#define HOUT 1280          // HG + HL

#define S1   9             // split-K GEMM1: 9216 -> Kc=1024 (32 tiles)
#define S2   8             // split-K out GEMM: 1024 -> Kc=128
#define S3   2             // split-K hl GEMM:  256 -> Kc=128

// ---------------- scratch (device globals; no allocation allowed) ----------
__device__ float h1_buf[BB * HGN];           // fp32 h1 (consumed by reduce-split only)
__device__ float part1[S1 * BB * HGN];
__device__ float part2[S2 * BB * HOUT];
__device__ float part3[S3 * BB * HOUT];

// bf16 hi/lo operands. A-side: [rows][K]. B-side: natural [K][N] (NO transpose).
__device__ __align__(16) __nv_bfloat16 g_h [BB * GDIM],  g_l [BB * GDIM];
__device__ __align__(16) __nv_bfloat16 h1_h[BB * HGN],   h1_l[BB * HGN];
__device__ __align__(16) __nv_bfloat16 h2_h[BB * HLN],   h2_l[BB * HLN];
__device__ __align__(16) __nv_bfloat16 w1_h[GDIM * HGN], w1_l[GDIM * HGN];
__device__ __align__(16) __nv_bfloat16 w3_h[HGN * HOUT], w3_l[HGN * HOUT];
__device__ __align__(16) __nv_bfloat16 w4_h[HLN * HOUT], w4_l[HLN * HOUT];

// ---------------- PTX helpers ----------------------------------------------
__device__ __forceinline__ void cp16(uint32_t smem_dst, const void* gsrc) {
    asm volatile("cp.async.cg.shared.global [%0], [%1], 16;"
                 :: "r"(smem_dst), "l"(gsrc) : "memory");
}
__device__ __forceinline__ void cp_commit() {
    asm volatile("cp.async.commit_group;" ::: "memory");
}
template<int NG>
__device__ __forceinline__ void cp_wait() {
    asm volatile("cp.async.wait_group %0;" :: "n"(NG) : "memory");
}
__device__ __forceinline__ void ldm_x4(uint32_t* r, uint32_t addr) {
    asm volatile("ldmatrix.sync.aligned.m8n8.x4.shared.b16 {%0,%1,%2,%3}, [%4];"
                 : "=r"(r[0]), "=r"(r[1]), "=r"(r[2]), "=r"(r[3]) : "r"(addr));
}
__device__ __forceinline__ void ldm_x4_t(uint32_t* r, uint32_t addr) {
    asm volatile("ldmatrix.sync.aligned.m8n8.x4.trans.shared.b16 {%0,%1,%2,%3}, [%4];"
                 : "=r"(r[0]), "=r"(r[1]), "=r"(r[2]), "=r"(r[3]) : "r"(addr));
}
__device__ __forceinline__ void mma_bf16(float* c, const uint32_t* a, const uint32_t* b) {
    asm volatile("mma.sync.aligned.m16n8k16.row.col.f32.bf16.bf16.f32 "
                 "{%0,%1,%2,%3}, {%4,%5,%6,%7}, {%8,%9}, {%0,%1,%2,%3};"
                 : "+f"(c[0]), "+f"(c[1]), "+f"(c[2]), "+f"(c[3])
                 : "r"(a[0]), "r"(a[1]), "r"(a[2]), "r"(a[3]),
                   "r"(b[0]), "r"(b[1]));
}
__device__ __forceinline__ void split_store(float x, __nv_bfloat16* ph, __nv_bfloat16* pl) {
    __nv_bfloat16 h = __float2bfloat16(x);
    *ph = h;
    *pl = __float2bfloat16(x - __bfloat162float(h));
}

// ---------------- foveation (writes bf16 hi/lo directly) -------------------
__global__ void foveate_kernel(const float* __restrict__ img,
                               const float* __restrict__ loc) {
    int idx = blockIdx.x * blockDim.x + threadIdx.x;
    if (idx >= BB * GDIM) return;
    int b  = idx / GDIM;
    int r  = idx - b * GDIM;
    int z  = r / (CC * RET * RET);
    int r2 = r - z * (CC * RET * RET);
    int c  = r2 / (RET * RET);
    int p  = r2 - c * (RET * RET);
    int y  = p >> 5;
    int x  = p & 31;

    float dr = (loc[b * 2 + 0] + 1.0f) * 0.5f * (float)WWD;
    float dc = (loc[b * 2 + 1] + 1.0f) * 0.5f * (float)WWD;
    int half = 16 << z;
    int top  = (int)(dr - (float)half);
    int left = (int)(dc - (float)half);

    const float* im = img + ((size_t)b * CC + c) * (HH * WWD);
    float v;
    if (z == 0) {
        v = im[(top + y) * WWD + (left + x)];
    } else {
        int off = (z == 2) ? 1 : 0;
        int yy = top  + (y << z) + off;
        int xx = left + (x << z) + off;
        const float* p0 = im + yy * WWD + xx;
        v = 0.25f * (p0[0] + p0[1] + p0[WWD] + p0[WWD + 1]);
    }
    split_store(v, &g_h[idx], &g_l[idx]);
}

// ---------------- location FC (K=2), writes hi/lo --------------------------
__global__ void loc_fc_kernel(const float* __restrict__ loc,
                              const float* __restrict__ W2,
                              const float* __restrict__ b2) {
    int b = blockIdx.x;
    int n = threadIdx.x;
    float l0 = loc[b * 2 + 0];
    float l1 = loc[b * 2 + 1];
    float v = fmaf(l0, W2[n], fmaf(l1, W2[HLN + n], b2[n]));
    v = fmaxf(v, 0.0f);
    split_store(v, &h2_h[b * HLN + n], &h2_l[b * HLN + n]);
}

// ---------------- fp32 -> bf16 hi/lo split (element-wise, layout kept) -----
__global__ void conv_split_kernel(const float* __restrict__ in,
                                  __nv_bfloat16* __restrict__ oh,
                                  __nv_bfloat16* __restrict__ ol, int n2) {
    int i = blockIdx.x * 256 + threadIdx.x;
    if (i >= n2) return;
    float2 v = ((const float2*)in)[i];
    __nv_bfloat16 h0 = __float2bfloat16(v.x);
    __nv_bfloat16 h1 = __float2bfloat16(v.y);
    float r0 = v.x - __bfloat162float(h0);
    float r1 = v.y - __bfloat162float(h1);
    ((__nv_bfloat162*)oh)[i] = __halves2bfloat162(h0, h1);
    ((__nv_bfloat162*)ol)[i] = __halves2bfloat162(__float2bfloat16(r0),
                                                  __float2bfloat16(r1));
}

// ---------------- split-bf16 tensor-core split-K GEMM ----------------------
// part[z][M][N] = A[M x Kc chunk z] @ B[chunk z x N]
// A ~ Ah+Al row-major [M][K]; B ~ Bh+Bl row-major [K][N] (ldmatrix.trans).
// 3-pass: Ah*Bh + Al*Bh + Ah*Bl, fp32 accum.  BM=BN=64, BK=32, 4 warps.
// sA rows 80 B (40 b16), sB rows 144 B (72 b16): both conflict-free for LDSM.
__global__ __launch_bounds__(128, 4)
void mma_gemm_kernel(const __nv_bfloat16* __restrict__ Ah,
                     const __nv_bfloat16* __restrict__ Al,
                     const __nv_bfloat16* __restrict__ Bh,
                     const __nv_bfloat16* __restrict__ Bl,
                     float* __restrict__ part, int M, int N, int K, int Kc) {
    __shared__ __nv_bfloat16 sA[2][2][64][40];   // [stage][h/l][m][k]
    __shared__ __nv_bfloat16 sB[2][2][32][72];   // [stage][h/l][k][n]

    const int tid  = threadIdx.x;
    const int lane = tid & 31;
    const int warp = tid >> 5;
    const int bm   = blockIdx.y;
    const int bn   = blockIdx.x;
    const int sz   = blockIdx.z;
    const int kbase = sz * Kc;
    const int T     = Kc / 32;
    const int wm = (warp & 1) * 32;
    const int wn = (warp >> 1) * 32;

    const uint32_t sa0 = (uint32_t)__cvta_generic_to_shared(&sA[0][0][0][0]);
    const uint32_t sb0 = (uint32_t)__cvta_generic_to_shared(&sB[0][0][0][0]);
    // byte strides: sA stage=10240, h/l=5120, row=80 ; sB stage=9216, h/l=4608, row=144

    auto load_stage = [&](int it, int s) {
        const int k0 = kbase + it * 32;
        // A: per h/l, 64 rows x 32 b16 = 64 B/row -> 256 chunks; 512 total / 128 thr
        #pragma unroll
        for (int t = 0; t < 4; t++) {
            int hl  = t >> 1;
            int id2 = (t & 1) * 128 + tid;     // 0..255
            int r   = id2 >> 2;                // 0..63
            int c   = (id2 & 3) * 8;           // b16 col
            const __nv_bfloat16* src = (hl ? Al : Ah) + (size_t)(bm * 64 + r) * K + k0 + c;
            cp16(sa0 + (uint32_t)(s * 10240 + hl * 5120 + r * 80 + c * 2), src);
        }
        // B: per h/l, 32 rows x 64 b16 = 128 B/row -> 256 chunks; 512 total
        #pragma unroll
        for (int t = 0; t < 4; t++) {
            int hl  = t >> 1;
            int id2 = (t & 1) * 128 + tid;     // 0..255
            int r   = id2 >> 3;                // 0..31 (k)
            int c   = (id2 & 7) * 8;           // b16 col (n)
            const __nv_bfloat16* src = (hl ? Bl : Bh) + (size_t)(k0 + r) * N + bn * 64 + c;
            cp16(sb0 + (uint32_t)(s * 9216 + hl * 4608 + r * 144 + c * 2), src);
        }
        cp_commit();
    };

    float acc[2][4][4] = {};

    // A ldmatrix lane offset (bytes within one h/l buffer)
    const uint32_t a_off = (uint32_t)((wm + (lane & 15)) * 80 + (lane >> 4) * 16);
    // B ldmatrix.trans lane addressing: matrix m=lane>>3 (0..3), row j=lane&7
    //   m&1 -> k-half (+8 rows), m>>1 -> n-half (+8 cols)
    const int bm_m = lane >> 3;
    const int bm_j = lane & 7;
    const uint32_t b_row_part = (uint32_t)(((bm_m & 1) * 8 + bm_j) * 144);
    const uint32_t b_col_part = (uint32_t)((wn + (bm_m >> 1) * 8) * 2);

    load_stage(0, 0);
    int buf = 0;
    for (int it = 0; it < T; it++) {
        if (it + 1 < T) { load_stage(it + 1, buf ^ 1); cp_wait<1>(); }
        else            { cp_wait<0>(); }
        __syncthreads();

        const uint32_t sa_s = sa0 + buf * 10240;
        const uint32_t sb_s = sb0 + buf * 9216;

        #pragma unroll
        for (int k16 = 0; k16 < 32; k16 += 16) {
            uint32_t aH[2][4], aL[2][4], bH[4][2], bL[4][2], tmp[4];
            #pragma unroll
            for (int mt = 0; mt < 2; mt++) {
                ldm_x4(aH[mt], sa_s        + a_off + mt * (16 * 80) + k16 * 2);
                ldm_x4(aL[mt], sa_s + 5120 + a_off + mt * (16 * 80) + k16 * 2);
            }
            #pragma unroll
            for (int np = 0; np < 2; np++) {
                uint32_t addr = b_row_part + (uint32_t)(k16 * 144)
                              + b_col_part + (uint32_t)(np * 16 * 2);
                ldm_x4_t(tmp, sb_s + addr);
                bH[np * 2][0] = tmp[0];     bH[np * 2][1] = tmp[1];
                bH[np * 2 + 1][0] = tmp[2]; bH[np * 2 + 1][1] = tmp[3];
                ldm_x4_t(tmp, sb_s + 4608 + addr);
                bL[np * 2][0] = tmp[0];     bL[np * 2][1] = tmp[1];
                bL[np * 2 + 1][0] = tmp[2]; bL[np * 2 + 1][1] = tmp[3];
            }
            #pragma unroll
            for (int mt = 0; mt < 2; mt++)
                #pragma unroll
                for (int nt = 0; nt < 4; nt++) {
                    mma_bf16(acc[mt][nt], aH[mt], bH[nt]);
                    mma_bf16(acc[mt][nt], aL[mt], bH[nt]);
                    mma_bf16(acc[mt][nt], aH[mt], bL[nt]);
                }
        }
        __syncthreads();
        buf ^= 1;
    }

    // epilogue: raw partials (layout proven in R9)
    float* pout = part + (size_t)sz * M * N;
    const int gm  = bm * 64 + wm + (lane >> 2);
    const int gn0 = bn * 64 + wn + (lane & 3) * 2;
    #pragma unroll
    for (int mt = 0; mt < 2; mt++)
        #pragma unroll
        for (int nt = 0; nt < 4; nt++) {
            int row = gm + mt * 16;
            int col = gn0 + nt * 8;
            *(float2*)&pout[(size_t)row * N + col] =
                make_float2(acc[mt][nt][0], acc[mt][nt][1]);
            *(float2*)&pout[(size_t)(row + 8) * N + col] =
                make_float2(acc[mt][nt][2], acc[mt][nt][3]);
        }
}

// ------- reduce 1: h1 = relu(sum_s part1 + b1); writes fp32 + bf16 hi/lo ---
__global__ void reduce1_kernel(const float* __restrict__ b1) {
    int idx4 = blockIdx.x * blockDim.x + threadIdx.x;
    if (idx4 >= BB * HGN / 4) return;
    int idx = idx4 * 4;
    int n   = idx % HGN;
    float4 s = *(const float4*)(part1 + idx);
    #pragma unroll
    for (int z = 1; z < S1; z++) {
        float4 v = *(const float4*)(part1 + (size_t)z * BB * HGN + idx);
        s.x += v.x; s.y += v.y; s.z += v.z; s.w += v.w;
    }
    float4 bv = *(const float4*)(b1 + n);
    s.x = fmaxf(s.x + bv.x, 0.0f);
    s.y = fmaxf(s.y + bv.y, 0.0f);
    s.z = fmaxf(s.z + bv.z, 0.0f);
    s.w = fmaxf(s.w + bv.w, 0.0f);
    // split to bf16 hi/lo directly (h1 fp32 never re-read elsewhere)
    __nv_bfloat16 hx = __float2bfloat16(s.x), hy = __float2bfloat16(s.y);
    __nv_bfloat16 hz = __float2bfloat16(s.z), hw = __float2bfloat16(s.w);
    ((__nv_bfloat162*)h1_h)[idx4 * 2]     = __halves2bfloat162(hx, hy);
    ((__nv_bfloat162*)h1_h)[idx4 * 2 + 1] = __halves2bfloat162(hz, hw);
    ((__nv_bfloat162*)h1_l)[idx4 * 2] = __halves2bfloat162(
        __float2bfloat16(s.x - __bfloat162float(hx)),
        __float2bfloat16(s.y - __bfloat162float(hy)));
    ((__nv_bfloat162*)h1_l)[idx4 * 2 + 1] = __halves2bfloat162(
        __float2bfloat16(s.z - __bfloat162float(hz)),
        __float2bfloat16(s.w - __bfloat162float(hw)));
}

// ---------------- final reduce: out = relu(Σpart2+b3) + relu(Σpart3+b4) ----
__global__ void final_reduce_kernel(const float* __restrict__ b3,
                                    const float* __restrict__ b4,
                                    float* __restrict__ out) {
    int idx4 = blockIdx.x * blockDim.x + threadIdx.x;
    if (idx4 >= BB * HOUT / 4) return;
    int idx = idx4 * 4;
    int n   = idx % HOUT;

    float4 sg = *(const float4*)(part2 + idx);
    #pragma unroll
    for (int z = 1; z < S2; z++) {
        float4 v = *(const float4*)(part2 + (size_t)z * BB * HOUT + idx);
        sg.x += v.x; sg.y += v.y; sg.z += v.z; sg.w += v.w;
    }
    float4 sl = *(const float4*)(part3 + idx);
    #pragma unroll
    for (int z = 1; z < S3; z++) {
        float4 v = *(const float4*)(part3 + (size_t)z * BB * HOUT + idx);
        sl.x += v.x; sl.y += v.y; sl.z += v.z; sl.w += v.w;
    }
    float4 g3 = *(const float4*)(b3 + n);
    float4 g4 = *(const float4*)(b4 + n);
    float4 o;
    o.x = fmaxf(sg.x + g3.x, 0.0f) + fmaxf(sl.x + g4.x, 0.0f);
    o.y = fmaxf(sg.y + g3.y, 0.0f) + fmaxf(sl.y + g4.y, 0.0f);
    o.z = fmaxf(sg.z + g3.z, 0.0f) + fmaxf(sl.z + g4.z, 0.0f);
    o.w = fmaxf(sg.w + g3.w, 0.0f) + fmaxf(sl.w + g4.w, 0.0f);
    *(float4*)(out + idx) = o;
}

// ---------------- launch ----------------------------------------------------
extern "C" void kernel_launch(void* const* d_in, const int* in_sizes, int n_in,
                              void* d_out, int out_size) {
    const float* images    = (const float*)d_in[0];
    const float* locations = (const float*)d_in[1];
    const float* W1        = (const float*)d_in[2];
    const float* b1        = (const float*)d_in[3];
    const float* W2        = (const float*)d_in[4];
    const float* b2        = (const float*)d_in[5];
    const float* W3        = (const float*)d_in[6];
    const float* b3        = (const float*)d_in[7];
    const float* W4        = (const float*)d_in[8];
    const float* b4        = (const float*)d_in[9];
    float* out = (float*)d_out;
    (void)in_sizes; (void)n_in; (void)out_size;

    void *p1p, *p2p, *p3p;
    void *ghp, *glp, *h1hp, *h1lp, *h2hp, *h2lp;
    void *w1hp, *w1lp, *w3hp, *w3lp, *w4hp, *w4lp;
    cudaGetSymbolAddress(&p1p,  part1);
    cudaGetSymbolAddress(&p2p,  part2);
    cudaGetSymbolAddress(&p3p,  part3);
    cudaGetSymbolAddress(&ghp,  g_h);  cudaGetSymbolAddress(&glp,  g_l);
    cudaGetSymbolAddress(&h1hp, h1_h); cudaGetSymbolAddress(&h1lp, h1_l);
    cudaGetSymbolAddress(&h2hp, h2_h); cudaGetSymbolAddress(&h2lp, h2_l);
    cudaGetSymbolAddress(&w1hp, w1_h); cudaGetSymbolAddress(&w1lp, w1_l);
    cudaGetSymbolAddress(&w3hp, w3_h); cudaGetSymbolAddress(&w3lp, w3_l);
    cudaGetSymbolAddress(&w4hp, w4_h); cudaGetSymbolAddress(&w4lp, w4_l);

    // 1) producers write bf16 hi/lo directly
    foveate_kernel<<<(BB * GDIM + 255) / 256, 256>>>(images, locations);
    loc_fc_kernel<<<BB, HLN>>>(locations, W2, b2);

    // 2) element-wise W splits (layout preserved, no transpose)
    conv_split_kernel<<<(HLN * HOUT / 2 + 255) / 256, 256>>>(
        W4, (__nv_bfloat16*)w4hp, (__nv_bfloat16*)w4lp, HLN * HOUT / 2);
    conv_split_kernel<<<(GDIM * HGN / 2 + 255) / 256, 256>>>(
        W1, (__nv_bfloat16*)w1hp, (__nv_bfloat16*)w1lp, GDIM * HGN / 2);
    conv_split_kernel<<<(HGN * HOUT / 2 + 255) / 256, 256>>>(
        W3, (__nv_bfloat16*)w3hp, (__nv_bfloat16*)w3lp, HGN * HOUT / 2);

    // 3) hl partials: h2 @ W4  (M=256, N=1280, K=256, S=2)
    mma_gemm_kernel<<<dim3(HOUT / 64, BB / 64, S3), 128>>>(
        (const __nv_bfloat16*)h2hp, (const __nv_bfloat16*)h2lp,
        (const __nv_bfloat16*)w4hp, (const __nv_bfloat16*)w4lp,
        (float*)p3p, BB, HOUT, HLN, HLN / S3);

    // 4) GEMM1 partials: g @ W1 (M=256, N=1024, K=9216, S=9)
    mma_gemm_kernel<<<dim3(HGN / 64, BB / 64, S1), 128>>>(
        (const __nv_bfloat16*)ghp, (const __nv_bfloat16*)glp,
        (const __nv_bfloat16*)w1hp, (const __nv_bfloat16*)w1lp,
        (float*)p1p, BB, HGN, GDIM, GDIM / S1);

    // 5) h1 = relu(sum part1 + b1) -> bf16 hi/lo directly
    reduce1_kernel<<<(BB * HGN / 4 + 255) / 256, 256>>>(b1);

    // 6) out partials: h1 @ W3 (M=256, N=1280, K=1024, S=8)
    mma_gemm_kernel<<<dim3(HOUT / 64, BB / 64, S2), 128>>>(
        (const __nv_bfloat16*)h1hp, (const __nv_bfloat16*)h1lp,
        (const __nv_bfloat16*)w3hp, (const __nv_bfloat16*)w3lp,
        (float*)p2p, BB, HOUT, HGN, HGN / S2);

    // 7) out = relu(sum part2 + b3) + relu(sum part3 + b4)
    final_reduce_kernel<<<(BB * HOUT / 4 + 255) / 256, 256>>>(b3, b4, out);
}

// round 11
// speedup vs baseline: 2.3404x; 1.0675x over previous
#include <cuda_runtime.h>
#include <cuda_bf16.h>
#include <cstdint>

// ---------------- problem constants ----------------
#define BB   256
#define CC   3
#define HH   224
#define WWD  224
#define RET  32
#define GDIM 9216          // 3 * 3 * 32 * 32
#define HGN  1024
#define HLN  256
#define HOUT 1280          // HG + HL

#define S1   9             // split-K GEMM1: 9216 -> Kc=1024 (32 tiles)
#define S2   8             // split-K out GEMM: 1024 -> Kc=128
#define S3   2             // split-K hl GEMM:  256 -> Kc=128

// ---------------- scratch (device globals; no allocation allowed) ----------
__device__ float part1[S1 * BB * HGN];
__device__ float part2[S2 * BB * HOUT];
__device__ float part3[S3 * BB * HOUT];

// bf16 hi/lo operands. A-side: [rows][K]. B-side: natural [K][N] (NO transpose).
__device__ __align__(16) __nv_bfloat16 g_h [BB * GDIM],  g_l [BB * GDIM];
__device__ __align__(16) __nv_bfloat16 h1_h[BB * HGN],   h1_l[BB * HGN];
__device__ __align__(16) __nv_bfloat16 h2_h[BB * HLN],   h2_l[BB * HLN];
__device__ __align__(16) __nv_bfloat16 w1_h[GDIM * HGN], w1_l[GDIM * HGN];
__device__ __align__(16) __nv_bfloat16 w3_h[HGN * HOUT], w3_l[HGN * HOUT];
__device__ __align__(16) __nv_bfloat16 w4_h[HLN * HOUT], w4_l[HLN * HOUT];

// ---------------- PTX helpers ----------------------------------------------
__device__ __forceinline__ void cp16(uint32_t smem_dst, const void* gsrc) {
    asm volatile("cp.async.cg.shared.global [%0], [%1], 16;"
                 :: "r"(smem_dst), "l"(gsrc) : "memory");
}
__device__ __forceinline__ void cp_commit() {
    asm volatile("cp.async.commit_group;" ::: "memory");
}
template<int NG>
__device__ __forceinline__ void cp_wait() {
    asm volatile("cp.async.wait_group %0;" :: "n"(NG) : "memory");
}
__device__ __forceinline__ void ldm_x4(uint32_t* r, uint32_t addr) {
    asm volatile("ldmatrix.sync.aligned.m8n8.x4.shared.b16 {%0,%1,%2,%3}, [%4];"
                 : "=r"(r[0]), "=r"(r[1]), "=r"(r[2]), "=r"(r[3]) : "r"(addr));
}
__device__ __forceinline__ void ldm_x4_t(uint32_t* r, uint32_t addr) {
    asm volatile("ldmatrix.sync.aligned.m8n8.x4.trans.shared.b16 {%0,%1,%2,%3}, [%4];"
                 : "=r"(r[0]), "=r"(r[1]), "=r"(r[2]), "=r"(r[3]) : "r"(addr));
}
__device__ __forceinline__ void mma_bf16(float* c, const uint32_t* a, const uint32_t* b) {
    asm volatile("mma.sync.aligned.m16n8k16.row.col.f32.bf16.bf16.f32 "
                 "{%0,%1,%2,%3}, {%4,%5,%6,%7}, {%8,%9}, {%0,%1,%2,%3};"
                 : "+f"(c[0]), "+f"(c[1]), "+f"(c[2]), "+f"(c[3])
                 : "r"(a[0]), "r"(a[1]), "r"(a[2]), "r"(a[3]),
                   "r"(b[0]), "r"(b[1]));
}
// pack two fp32 into bf16x2 hi word + bf16x2 lo-residual word
__device__ __forceinline__ void split2(float x, float y,
                                       uint32_t& hw, uint32_t& lw) {
    __nv_bfloat16 hx = __float2bfloat16(x);
    __nv_bfloat16 hy = __float2bfloat16(y);
    __nv_bfloat162 h2 = __halves2bfloat162(hx, hy);
    __nv_bfloat162 l2 = __halves2bfloat162(
        __float2bfloat16(x - __bfloat162float(hx)),
        __float2bfloat16(y - __bfloat162float(hy)));
    hw = *(uint32_t*)&h2;
    lw = *(uint32_t*)&l2;
}

// ---------------- foveation (2 pixels/thread, bf16 hi/lo out) --------------
__global__ void foveate_kernel(const float* __restrict__ img,
                               const float* __restrict__ loc) {
    int idx2 = blockIdx.x * blockDim.x + threadIdx.x;
    if (idx2 >= BB * GDIM / 2) return;
    int idx = idx2 * 2;
    int b  = idx / GDIM;
    int r  = idx - b * GDIM;
    int z  = r / (CC * RET * RET);
    int r2 = r - z * (CC * RET * RET);
    int c  = r2 / (RET * RET);
    int p  = r2 - c * (RET * RET);
    int y  = p >> 5;
    int x  = p & 31;          // even

    float dr = (loc[b * 2 + 0] + 1.0f) * 0.5f * (float)WWD;
    float dc = (loc[b * 2 + 1] + 1.0f) * 0.5f * (float)WWD;
    int half = 16 << z;
    int top  = (int)(dr - (float)half);
    int left = (int)(dc - (float)half);

    const float* im = img + ((size_t)b * CC + c) * (HH * WWD);
    float v0, v1;
    if (z == 0) {
        const float* p0 = im + (top + y) * WWD + (left + x);
        v0 = p0[0];
        v1 = p0[1];
    } else {
        int off = (z == 2) ? 1 : 0;
        int yy  = top  + (y << z) + off;
        int xx  = left + (x << z) + off;
        int st  = 1 << z;
        const float* p0 = im + yy * WWD + xx;
        v0 = 0.25f * (p0[0] + p0[1] + p0[WWD] + p0[WWD + 1]);
        const float* p1 = p0 + st;
        v1 = 0.25f * (p1[0] + p1[1] + p1[WWD] + p1[WWD + 1]);
    }
    uint32_t hw, lw;
    split2(v0, v1, hw, lw);
    ((uint32_t*)g_h)[idx2] = hw;
    ((uint32_t*)g_l)[idx2] = lw;
}

// ---------------- location FC (K=2), writes hi/lo --------------------------
__global__ void loc_fc_kernel(const float* __restrict__ loc,
                              const float* __restrict__ W2,
                              const float* __restrict__ b2) {
    int b = blockIdx.x;
    int n = threadIdx.x * 2;                 // 128 threads, 2 cols each
    float l0 = loc[b * 2 + 0];
    float l1 = loc[b * 2 + 1];
    float v0 = fmaxf(fmaf(l0, W2[n],     fmaf(l1, W2[HLN + n],     b2[n])),     0.0f);
    float v1 = fmaxf(fmaf(l0, W2[n + 1], fmaf(l1, W2[HLN + n + 1], b2[n + 1])), 0.0f);
    uint32_t hw, lw;
    split2(v0, v1, hw, lw);
    ((uint32_t*)h2_h)[(b * HLN + n) / 2] = hw;
    ((uint32_t*)h2_l)[(b * HLN + n) / 2] = lw;
}

// -------- fp32 -> bf16 hi/lo split, 4 elems/thread (vectorized) ------------
__global__ void conv_split_kernel(const float* __restrict__ in,
                                  __nv_bfloat16* __restrict__ oh,
                                  __nv_bfloat16* __restrict__ ol, int n4) {
    int i = blockIdx.x * 256 + threadIdx.x;
    if (i >= n4) return;
    float4 v = ((const float4*)in)[i];
    uint2 hq, lq;
    split2(v.x, v.y, hq.x, lq.x);
    split2(v.z, v.w, hq.y, lq.y);
    ((uint2*)oh)[i] = hq;
    ((uint2*)ol)[i] = lq;
}

// ---------------- split-bf16 tensor-core split-K GEMM ----------------------
// part[z][M][N] = A[M x Kc chunk z] @ B[chunk z x N]
// A ~ Ah+Al row-major [M][K]; B ~ Bh+Bl row-major [K][N] (ldmatrix.trans).
// 3-pass: Ah*Bh + Al*Bh + Ah*Bl, fp32 accum.  BM=BN=64, BK=32, 4 warps.
__global__ __launch_bounds__(128, 4)
void mma_gemm_kernel(const __nv_bfloat16* __restrict__ Ah,
                     const __nv_bfloat16* __restrict__ Al,
                     const __nv_bfloat16* __restrict__ Bh,
                     const __nv_bfloat16* __restrict__ Bl,
                     float* __restrict__ part, int M, int N, int K, int Kc) {
    __shared__ __nv_bfloat16 sA[2][2][64][40];   // [stage][h/l][m][k]
    __shared__ __nv_bfloat16 sB[2][2][32][72];   // [stage][h/l][k][n]

    const int tid  = threadIdx.x;
    const int lane = tid & 31;
    const int warp = tid >> 5;
    const int bm   = blockIdx.y;
    const int bn   = blockIdx.x;
    const int sz   = blockIdx.z;
    const int kbase = sz * Kc;
    const int T     = Kc / 32;
    const int wm = (warp & 1) * 32;
    const int wn = (warp >> 1) * 32;

    const uint32_t sa0 = (uint32_t)__cvta_generic_to_shared(&sA[0][0][0][0]);
    const uint32_t sb0 = (uint32_t)__cvta_generic_to_shared(&sB[0][0][0][0]);

    auto load_stage = [&](int it, int s) {
        const int k0 = kbase + it * 32;
        #pragma unroll
        for (int t = 0; t < 4; t++) {
            int hl  = t >> 1;
            int id2 = (t & 1) * 128 + tid;
            int r   = id2 >> 2;
            int c   = (id2 & 3) * 8;
            const __nv_bfloat16* src = (hl ? Al : Ah) + (size_t)(bm * 64 + r) * K + k0 + c;
            cp16(sa0 + (uint32_t)(s * 10240 + hl * 5120 + r * 80 + c * 2), src);
        }
        #pragma unroll
        for (int t = 0; t < 4; t++) {
            int hl  = t >> 1;
            int id2 = (t & 1) * 128 + tid;
            int r   = id2 >> 3;
            int c   = (id2 & 7) * 8;
            const __nv_bfloat16* src = (hl ? Bl : Bh) + (size_t)(k0 + r) * N + bn * 64 + c;
            cp16(sb0 + (uint32_t)(s * 9216 + hl * 4608 + r * 144 + c * 2), src);
        }
        cp_commit();
    };

    float acc[2][4][4] = {};

    const uint32_t a_off = (uint32_t)((wm + (lane & 15)) * 80 + (lane >> 4) * 16);
    const int bm_m = lane >> 3;
    const int bm_j = lane & 7;
    const uint32_t b_row_part = (uint32_t)(((bm_m & 1) * 8 + bm_j) * 144);
    const uint32_t b_col_part = (uint32_t)((wn + (bm_m >> 1) * 8) * 2);

    load_stage(0, 0);
    int buf = 0;
    for (int it = 0; it < T; it++) {
        if (it + 1 < T) { load_stage(it + 1, buf ^ 1); cp_wait<1>(); }
        else            { cp_wait<0>(); }
        __syncthreads();

        const uint32_t sa_s = sa0 + buf * 10240;
        const uint32_t sb_s = sb0 + buf * 9216;

        #pragma unroll
        for (int k16 = 0; k16 < 32; k16 += 16) {
            uint32_t aH[2][4], aL[2][4], bH[4][2], bL[4][2], tmp[4];
            #pragma unroll
            for (int mt = 0; mt < 2; mt++) {
                ldm_x4(aH[mt], sa_s        + a_off + mt * (16 * 80) + k16 * 2);
                ldm_x4(aL[mt], sa_s + 5120 + a_off + mt * (16 * 80) + k16 * 2);
            }
            #pragma unroll
            for (int np = 0; np < 2; np++) {
                uint32_t addr = b_row_part + (uint32_t)(k16 * 144)
                              + b_col_part + (uint32_t)(np * 16 * 2);
                ldm_x4_t(tmp, sb_s + addr);
                bH[np * 2][0] = tmp[0];     bH[np * 2][1] = tmp[1];
                bH[np * 2 + 1][0] = tmp[2]; bH[np * 2 + 1][1] = tmp[3];
                ldm_x4_t(tmp, sb_s + 4608 + addr);
                bL[np * 2][0] = tmp[0];     bL[np * 2][1] = tmp[1];
                bL[np * 2 + 1][0] = tmp[2]; bL[np * 2 + 1][1] = tmp[3];
            }
            #pragma unroll
            for (int mt = 0; mt < 2; mt++)
                #pragma unroll
                for (int nt = 0; nt < 4; nt++) {
                    mma_bf16(acc[mt][nt], aH[mt], bH[nt]);
                    mma_bf16(acc[mt][nt], aL[mt], bH[nt]);
                    mma_bf16(acc[mt][nt], aH[mt], bL[nt]);
                }
        }
        __syncthreads();
        buf ^= 1;
    }

    float* pout = part + (size_t)sz * M * N;
    const int gm  = bm * 64 + wm + (lane >> 2);
    const int gn0 = bn * 64 + wn + (lane & 3) * 2;
    #pragma unroll
    for (int mt = 0; mt < 2; mt++)
        #pragma unroll
        for (int nt = 0; nt < 4; nt++) {
            int row = gm + mt * 16;
            int col = gn0 + nt * 8;
            *(float2*)&pout[(size_t)row * N + col] =
                make_float2(acc[mt][nt][0], acc[mt][nt][1]);
            *(float2*)&pout[(size_t)(row + 8) * N + col] =
                make_float2(acc[mt][nt][2], acc[mt][nt][3]);
        }
}

// ------- reduce 1: h1 = relu(sum_s part1 + b1) -> bf16 hi/lo directly ------
__global__ void reduce1_kernel(const float* __restrict__ b1) {
    int idx4 = blockIdx.x * blockDim.x + threadIdx.x;
    if (idx4 >= BB * HGN / 4) return;
    int idx = idx4 * 4;
    int n   = idx % HGN;
    float4 s = *(const float4*)(part1 + idx);
    #pragma unroll
    for (int z = 1; z < S1; z++) {
        float4 v = *(const float4*)(part1 + (size_t)z * BB * HGN + idx);
        s.x += v.x; s.y += v.y; s.z += v.z; s.w += v.w;
    }
    float4 bv = *(const float4*)(b1 + n);
    s.x = fmaxf(s.x + bv.x, 0.0f);
    s.y = fmaxf(s.y + bv.y, 0.0f);
    s.z = fmaxf(s.z + bv.z, 0.0f);
    s.w = fmaxf(s.w + bv.w, 0.0f);
    uint2 hq, lq;
    split2(s.x, s.y, hq.x, lq.x);
    split2(s.z, s.w, hq.y, lq.y);
    ((uint2*)h1_h)[idx4] = hq;
    ((uint2*)h1_l)[idx4] = lq;
}

// ---------------- final reduce: out = relu(Σpart2+b3) + relu(Σpart3+b4) ----
__global__ void final_reduce_kernel(const float* __restrict__ b3,
                                    const float* __restrict__ b4,
                                    float* __restrict__ out) {
    int idx4 = blockIdx.x * blockDim.x + threadIdx.x;
    if (idx4 >= BB * HOUT / 4) return;
    int idx = idx4 * 4;
    int n   = idx % HOUT;

    float4 sg = *(const float4*)(part2 + idx);
    #pragma unroll
    for (int z = 1; z < S2; z++) {
        float4 v = *(const float4*)(part2 + (size_t)z * BB * HOUT + idx);
        sg.x += v.x; sg.y += v.y; sg.z += v.z; sg.w += v.w;
    }
    float4 sl = *(const float4*)(part3 + idx);
    #pragma unroll
    for (int z = 1; z < S3; z++) {
        float4 v = *(const float4*)(part3 + (size_t)z * BB * HOUT + idx);
        sl.x += v.x; sl.y += v.y; sl.z += v.z; sl.w += v.w;
    }
    float4 g3 = *(const float4*)(b3 + n);
    float4 g4 = *(const float4*)(b4 + n);
    float4 o;
    o.x = fmaxf(sg.x + g3.x, 0.0f) + fmaxf(sl.x + g4.x, 0.0f);
    o.y = fmaxf(sg.y + g3.y, 0.0f) + fmaxf(sl.y + g4.y, 0.0f);
    o.z = fmaxf(sg.z + g3.z, 0.0f) + fmaxf(sl.z + g4.z, 0.0f);
    o.w = fmaxf(sg.w + g3.w, 0.0f) + fmaxf(sl.w + g4.w, 0.0f);
    *(float4*)(out + idx) = o;
}

// ---------------- launch ----------------------------------------------------
extern "C" void kernel_launch(void* const* d_in, const int* in_sizes, int n_in,
                              void* d_out, int out_size) {
    const float* images    = (const float*)d_in[0];
    const float* locations = (const float*)d_in[1];
    const float* W1        = (const float*)d_in[2];
    const float* b1        = (const float*)d_in[3];
    const float* W2        = (const float*)d_in[4];
    const float* b2        = (const float*)d_in[5];
    const float* W3        = (const float*)d_in[6];
    const float* b3        = (const float*)d_in[7];
    const float* W4        = (const float*)d_in[8];
    const float* b4        = (const float*)d_in[9];
    float* out = (float*)d_out;
    (void)in_sizes; (void)n_in; (void)out_size;

    void *p1p, *p2p, *p3p;
    void *ghp, *glp, *h1hp, *h1lp, *h2hp, *h2lp;
    void *w1hp, *w1lp, *w3hp, *w3lp, *w4hp, *w4lp;
    cudaGetSymbolAddress(&p1p,  part1);
    cudaGetSymbolAddress(&p2p,  part2);
    cudaGetSymbolAddress(&p3p,  part3);
    cudaGetSymbolAddress(&ghp,  g_h);  cudaGetSymbolAddress(&glp,  g_l);
    cudaGetSymbolAddress(&h1hp, h1_h); cudaGetSymbolAddress(&h1lp, h1_l);
    cudaGetSymbolAddress(&h2hp, h2_h); cudaGetSymbolAddress(&h2lp, h2_l);
    cudaGetSymbolAddress(&w1hp, w1_h); cudaGetSymbolAddress(&w1lp, w1_l);
    cudaGetSymbolAddress(&w3hp, w3_h); cudaGetSymbolAddress(&w3lp, w3_l);
    cudaGetSymbolAddress(&w4hp, w4_h); cudaGetSymbolAddress(&w4lp, w4_l);

    // 1) producers write bf16 hi/lo directly
    foveate_kernel<<<(BB * GDIM / 2 + 255) / 256, 256>>>(images, locations);
    loc_fc_kernel<<<BB, HLN / 2>>>(locations, W2, b2);

    // 2) element-wise W splits (vectorized x4)
    conv_split_kernel<<<(HLN * HOUT / 4 + 255) / 256, 256>>>(
        W4, (__nv_bfloat16*)w4hp, (__nv_bfloat16*)w4lp, HLN * HOUT / 4);
    conv_split_kernel<<<(GDIM * HGN / 4 + 255) / 256, 256>>>(
        W1, (__nv_bfloat16*)w1hp, (__nv_bfloat16*)w1lp, GDIM * HGN / 4);
    conv_split_kernel<<<(HGN * HOUT / 4 + 255) / 256, 256>>>(
        W3, (__nv_bfloat16*)w3hp, (__nv_bfloat16*)w3lp, HGN * HOUT / 4);

    // 3) hl partials: h2 @ W4  (M=256, N=1280, K=256, S=2)
    mma_gemm_kernel<<<dim3(HOUT / 64, BB / 64, S3), 128>>>(
        (const __nv_bfloat16*)h2hp, (const __nv_bfloat16*)h2lp,
        (const __nv_bfloat16*)w4hp, (const __nv_bfloat16*)w4lp,
        (float*)p3p, BB, HOUT, HLN, HLN / S3);

    // 4) GEMM1 partials: g @ W1 (M=256, N=1024, K=9216, S=9)
    mma_gemm_kernel<<<dim3(HGN / 64, BB / 64, S1), 128>>>(
        (const __nv_bfloat16*)ghp, (const __nv_bfloat16*)glp,
        (const __nv_bfloat16*)w1hp, (const __nv_bfloat16*)w1lp,
        (float*)p1p, BB, HGN, GDIM, GDIM / S1);

    // 5) h1 = relu(sum part1 + b1) -> bf16 hi/lo directly
    reduce1_kernel<<<(BB * HGN / 4 + 255) / 256, 256>>>(b1);

    // 6) out partials: h1 @ W3 (M=256, N=1280, K=1024, S=8)
    mma_gemm_kernel<<<dim3(HOUT / 64, BB / 64, S2), 128>>>(
        (const __nv_bfloat16*)h1hp, (const __nv_bfloat16*)h1lp,
        (const __nv_bfloat16*)w3hp, (const __nv_bfloat16*)w3lp,
        (float*)p2p, BB, HOUT, HGN, HGN / S2);

    // 7) out = relu(sum part2 + b3) + relu(sum part3 + b4)
    final_reduce_kernel<<<(BB * HOUT / 4 + 255) / 256, 256>>>(b3, b4, out);
}

// round 13
// speedup vs baseline: 2.4703x; 1.0555x over previous
#include <cuda_runtime.h>
#include <cuda_bf16.h>
#include <cstdint>

// ---------------- problem constants ----------------
#define BB   256
#define CC   3
#define HH   224
#define WWD  224
#define RET  32
#define GDIM 9216          // 3 * 3 * 32 * 32
#define HGN  1024
#define HLN  256
#define HOUT 1280          // HG + HL

#define S1   9             // split-K GEMM1: 9216 -> Kc=1024 (32 tiles)
#define S2   4             // split-K out GEMM: 1024 -> Kc=256 (single wave)
#define S3   2             // split-K hl GEMM:  256 -> Kc=128

// ---------------- scratch (device globals; no allocation allowed) ----------
__device__ float part1[S1 * BB * HGN];
__device__ float part2[S2 * BB * HOUT];
__device__ float part3[S3 * BB * HOUT];

// bf16 hi/lo operands. A-side: [rows][K]. B-side: natural [K][N].
__device__ __align__(16) __nv_bfloat16 g_h [BB * GDIM],  g_l [BB * GDIM];
__device__ __align__(16) __nv_bfloat16 h1_h[BB * HGN],   h1_l[BB * HGN];
__device__ __align__(16) __nv_bfloat16 h2_h[BB * HLN],   h2_l[BB * HLN];
__device__ __align__(16) __nv_bfloat16 w1_h[GDIM * HGN], w1_l[GDIM * HGN];
__device__ __align__(16) __nv_bfloat16 w3_h[HGN * HOUT], w3_l[HGN * HOUT];
__device__ __align__(16) __nv_bfloat16 w4_h[HLN * HOUT], w4_l[HLN * HOUT];

// ---------------- PTX helpers ----------------------------------------------
__device__ __forceinline__ void cp16(uint32_t smem_dst, const void* gsrc) {
    asm volatile("cp.async.cg.shared.global [%0], [%1], 16;"
                 :: "r"(smem_dst), "l"(gsrc) : "memory");
}
__device__ __forceinline__ void cp_commit() {
    asm volatile("cp.async.commit_group;" ::: "memory");
}
template<int NG>
__device__ __forceinline__ void cp_wait() {
    asm volatile("cp.async.wait_group %0;" :: "n"(NG) : "memory");
}
__device__ __forceinline__ void ldm_x4(uint32_t* r, uint32_t addr) {
    asm volatile("ldmatrix.sync.aligned.m8n8.x4.shared.b16 {%0,%1,%2,%3}, [%4];"
                 : "=r"(r[0]), "=r"(r[1]), "=r"(r[2]), "=r"(r[3]) : "r"(addr));
}
__device__ __forceinline__ void ldm_x4_t(uint32_t* r, uint32_t addr) {
    asm volatile("ldmatrix.sync.aligned.m8n8.x4.trans.shared.b16 {%0,%1,%2,%3}, [%4];"
                 : "=r"(r[0]), "=r"(r[1]), "=r"(r[2]), "=r"(r[3]) : "r"(addr));
}
__device__ __forceinline__ void mma_bf16(float* c, const uint32_t* a, const uint32_t* b) {
    asm volatile("mma.sync.aligned.m16n8k16.row.col.f32.bf16.bf16.f32 "
                 "{%0,%1,%2,%3}, {%4,%5,%6,%7}, {%8,%9}, {%0,%1,%2,%3};"
                 : "+f"(c[0]), "+f"(c[1]), "+f"(c[2]), "+f"(c[3])
                 : "r"(a[0]), "r"(a[1]), "r"(a[2]), "r"(a[3]),
                   "r"(b[0]), "r"(b[1]));
}
// pack two fp32 into bf16x2 hi word + bf16x2 lo-residual word
__device__ __forceinline__ void split2(float x, float y,
                                       uint32_t& hw, uint32_t& lw) {
    __nv_bfloat16 hx = __float2bfloat16(x);
    __nv_bfloat16 hy = __float2bfloat16(y);
    __nv_bfloat162 h2 = __halves2bfloat162(hx, hy);
    __nv_bfloat162 l2 = __halves2bfloat162(
        __float2bfloat16(x - __bfloat162float(hx)),
        __float2bfloat16(y - __bfloat162float(hy)));
    hw = *(uint32_t*)&h2;
    lw = *(uint32_t*)&l2;
}

// ------- fused W splits: W4 | W1 | W3, 8 elems/thread, one launch ----------
#define W4_C (HLN * HOUT / 8)
#define W1_C (GDIM * HGN / 8)
#define W3_C (HGN * HOUT / 8)
#define CONV_TOT (W4_C + W1_C + W3_C)

__global__ void conv_all_kernel(const float* __restrict__ W1p,
                                const float* __restrict__ W3p,
                                const float* __restrict__ W4p) {
    int i = blockIdx.x * 256 + threadIdx.x;
    if (i >= CONV_TOT) return;
    const float* src;
    __nv_bfloat16 *oh, *ol;
    if (i < W4_C)              { src = W4p; oh = w4_h; ol = w4_l; }
    else if (i < W4_C + W1_C)  { i -= W4_C; src = W1p; oh = w1_h; ol = w1_l; }
    else                       { i -= W4_C + W1_C; src = W3p; oh = w3_h; ol = w3_l; }
    float4 a = ((const float4*)src)[i * 2];
    float4 b = ((const float4*)src)[i * 2 + 1];
    uint4 hq, lq;
    split2(a.x, a.y, hq.x, lq.x);
    split2(a.z, a.w, hq.y, lq.y);
    split2(b.x, b.y, hq.z, lq.z);
    split2(b.z, b.w, hq.w, lq.w);
    ((uint4*)oh)[i] = hq;
    ((uint4*)ol)[i] = lq;
}

// ------- fused foveation (2 px/thread) + location FC -----------------------
#define FOV_BLOCKS (BB * GDIM / 2 / 256)    // 4608
#define LOC_BLOCKS (BB / 2)                 // 128 (2 batches per 256-thr block)

__global__ void fov_loc_kernel(const float* __restrict__ img,
                               const float* __restrict__ loc,
                               const float* __restrict__ W2,
                               const float* __restrict__ b2) {
    if (blockIdx.x >= FOV_BLOCKS) {
        // location FC: 128 extra blocks, 256 thr -> 2 batches per block
        int bb = (blockIdx.x - FOV_BLOCKS) * 2 + (threadIdx.x >> 7);
        int n  = (threadIdx.x & 127) * 2;
        float l0 = loc[bb * 2 + 0];
        float l1 = loc[bb * 2 + 1];
        float v0 = fmaxf(fmaf(l0, W2[n],     fmaf(l1, W2[HLN + n],     b2[n])),     0.0f);
        float v1 = fmaxf(fmaf(l0, W2[n + 1], fmaf(l1, W2[HLN + n + 1], b2[n + 1])), 0.0f);
        uint32_t hw, lw;
        split2(v0, v1, hw, lw);
        ((uint32_t*)h2_h)[(bb * HLN + n) / 2] = hw;
        ((uint32_t*)h2_l)[(bb * HLN + n) / 2] = lw;
        return;
    }
    int idx2 = blockIdx.x * 256 + threadIdx.x;
    int idx = idx2 * 2;
    int b  = idx / GDIM;
    int r  = idx - b * GDIM;
    int z  = r / (CC * RET * RET);
    int r2 = r - z * (CC * RET * RET);
    int c  = r2 / (RET * RET);
    int p  = r2 - c * (RET * RET);
    int y  = p >> 5;
    int x  = p & 31;          // even

    float dr = (loc[b * 2 + 0] + 1.0f) * 0.5f * (float)WWD;
    float dc = (loc[b * 2 + 1] + 1.0f) * 0.5f * (float)WWD;
    int half = 16 << z;
    int top  = (int)(dr - (float)half);
    int left = (int)(dc - (float)half);

    const float* im = img + ((size_t)b * CC + c) * (HH * WWD);
    float v0, v1;
    if (z == 0) {
        const float* p0 = im + (top + y) * WWD + (left + x);
        v0 = p0[0];
        v1 = p0[1];
    } else {
        int off = (z == 2) ? 1 : 0;
        int yy  = top  + (y << z) + off;
        int xx  = left + (x << z) + off;
        int st  = 1 << z;
        const float* p0 = im + yy * WWD + xx;
        v0 = 0.25f * (p0[0] + p0[1] + p0[WWD] + p0[WWD + 1]);
        const float* p1 = p0 + st;
        v1 = 0.25f * (p1[0] + p1[1] + p1[WWD] + p1[WWD + 1]);
    }
    uint32_t hw, lw;
    split2(v0, v1, hw, lw);
    ((uint32_t*)g_h)[idx2] = hw;
    ((uint32_t*)g_l)[idx2] = lw;
}

// ---------------- split-bf16 tensor-core split-K GEMM (proven core) --------
__global__ __launch_bounds__(128, 4)
void mma_gemm_kernel(const __nv_bfloat16* __restrict__ Ah,
                     const __nv_bfloat16* __restrict__ Al,
                     const __nv_bfloat16* __restrict__ Bh,
                     const __nv_bfloat16* __restrict__ Bl,
                     float* __restrict__ part, int M, int N, int K, int Kc) {
    __shared__ __nv_bfloat16 sA[2][2][64][40];   // [stage][h/l][m][k]
    __shared__ __nv_bfloat16 sB[2][2][32][72];   // [stage][h/l][k][n]

    const int tid  = threadIdx.x;
    const int lane = tid & 31;
    const int warp = tid >> 5;
    const int bm   = blockIdx.y;
    const int bn   = blockIdx.x;
    const int sz   = blockIdx.z;
    const int kbase = sz * Kc;
    const int T     = Kc / 32;
    const int wm = (warp & 1) * 32;
    const int wn = (warp >> 1) * 32;

    const uint32_t sa0 = (uint32_t)__cvta_generic_to_shared(&sA[0][0][0][0]);
    const uint32_t sb0 = (uint32_t)__cvta_generic_to_shared(&sB[0][0][0][0]);

    auto load_stage = [&](int it, int s) {
        const int k0 = kbase + it * 32;
        #pragma unroll
        for (int t = 0; t < 4; t++) {
            int hl  = t >> 1;
            int id2 = (t & 1) * 128 + tid;
            int r   = id2 >> 2;
            int c   = (id2 & 3) * 8;
            const __nv_bfloat16* src = (hl ? Al : Ah) + (size_t)(bm * 64 + r) * K + k0 + c;
            cp16(sa0 + (uint32_t)(s * 10240 + hl * 5120 + r * 80 + c * 2), src);
        }
        #pragma unroll
        for (int t = 0; t < 4; t++) {
            int hl  = t >> 1;
            int id2 = (t & 1) * 128 + tid;
            int r   = id2 >> 3;
            int c   = (id2 & 7) * 8;
            const __nv_bfloat16* src = (hl ? Bl : Bh) + (size_t)(k0 + r) * N + bn * 64 + c;
            cp16(sb0 + (uint32_t)(s * 9216 + hl * 4608 + r * 144 + c * 2), src);
        }
        cp_commit();
    };

    float acc[2][4][4] = {};

    const uint32_t a_off = (uint32_t)((wm + (lane & 15)) * 80 + (lane >> 4) * 16);
    const int bm_m = lane >> 3;
    const int bm_j = lane & 7;
    const uint32_t b_row_part = (uint32_t)(((bm_m & 1) * 8 + bm_j) * 144);
    const uint32_t b_col_part = (uint32_t)((wn + (bm_m >> 1) * 8) * 2);

    load_stage(0, 0);
    int buf = 0;
    for (int it = 0; it < T; it++) {
        if (it + 1 < T) { load_stage(it + 1, buf ^ 1); cp_wait<1>(); }
        else            { cp_wait<0>(); }
        __syncthreads();

        const uint32_t sa_s = sa0 + buf * 10240;
        const uint32_t sb_s = sb0 + buf * 9216;

        #pragma unroll
        for (int k16 = 0; k16 < 32; k16 += 16) {
            uint32_t aH[2][4], aL[2][4], bH[4][2], bL[4][2], tmp[4];
            #pragma unroll
            for (int mt = 0; mt < 2; mt++) {
                ldm_x4(aH[mt], sa_s        + a_off + mt * (16 * 80) + k16 * 2);
                ldm_x4(aL[mt], sa_s + 5120 + a_off + mt * (16 * 80) + k16 * 2);
            }
            #pragma unroll
            for (int np = 0; np < 2; np++) {
                uint32_t addr = b_row_part + (uint32_t)(k16 * 144)
                              + b_col_part + (uint32_t)(np * 16 * 2);
                ldm_x4_t(tmp, sb_s + addr);
                bH[np * 2][0] = tmp[0];     bH[np * 2][1] = tmp[1];
                bH[np * 2 + 1][0] = tmp[2]; bH[np * 2 + 1][1] = tmp[3];
                ldm_x4_t(tmp, sb_s + 4608 + addr);
                bL[np * 2][0] = tmp[0];     bL[np * 2][1] = tmp[1];
                bL[np * 2 + 1][0] = tmp[2]; bL[np * 2 + 1][1] = tmp[3];
            }
            #pragma unroll
            for (int mt = 0; mt < 2; mt++)
                #pragma unroll
                for (int nt = 0; nt < 4; nt++) {
                    mma_bf16(acc[mt][nt], aH[mt], bH[nt]);
                    mma_bf16(acc[mt][nt], aL[mt], bH[nt]);
                    mma_bf16(acc[mt][nt], aH[mt], bL[nt]);
                }
        }
        __syncthreads();
        buf ^= 1;
    }

    float* pout = part + (size_t)sz * M * N;
    const int gm  = bm * 64 + wm + (lane >> 2);
    const int gn0 = bn * 64 + wn + (lane & 3) * 2;
    #pragma unroll
    for (int mt = 0; mt < 2; mt++)
        #pragma unroll
        for (int nt = 0; nt < 4; nt++) {
            int row = gm + mt * 16;
            int col = gn0 + nt * 8;
            *(float2*)&pout[(size_t)row * N + col] =
                make_float2(acc[mt][nt][0], acc[mt][nt][1]);
            *(float2*)&pout[(size_t)(row + 8) * N + col] =
                make_float2(acc[mt][nt][2], acc[mt][nt][3]);
        }
}

// ------- reduce 1: h1 = relu(sum_s part1 + b1) -> bf16 hi/lo directly ------
__global__ void reduce1_kernel(const float* __restrict__ b1) {
    int idx4 = blockIdx.x * blockDim.x + threadIdx.x;
    if (idx4 >= BB * HGN / 4) return;
    int idx = idx4 * 4;
    int n   = idx % HGN;
    float4 s = *(const float4*)(part1 + idx);
    #pragma unroll
    for (int z = 1; z < S1; z++) {
        float4 v = *(const float4*)(part1 + (size_t)z * BB * HGN + idx);
        s.x += v.x; s.y += v.y; s.z += v.z; s.w += v.w;
    }
    float4 bv = *(const float4*)(b1 + n);
    s.x = fmaxf(s.x + bv.x, 0.0f);
    s.y = fmaxf(s.y + bv.y, 0.0f);
    s.z = fmaxf(s.z + bv.z, 0.0f);
    s.w = fmaxf(s.w + bv.w, 0.0f);
    uint2 hq, lq;
    split2(s.x, s.y, hq.x, lq.x);
    split2(s.z, s.w, hq.y, lq.y);
    ((uint2*)h1_h)[idx4] = hq;
    ((uint2*)h1_l)[idx4] = lq;
}

// ---------------- final reduce: out = relu(Σpart2+b3) + relu(Σpart3+b4) ----
__global__ void final_reduce_kernel(const float* __restrict__ b3,
                                    const float* __restrict__ b4,
                                    float* __restrict__ out) {
    int idx4 = blockIdx.x * blockDim.x + threadIdx.x;
    if (idx4 >= BB * HOUT / 4) return;
    int idx = idx4 * 4;
    int n   = idx % HOUT;

    float4 sg = *(const float4*)(part2 + idx);
    #pragma unroll
    for (int z = 1; z < S2; z++) {
        float4 v = *(const float4*)(part2 + (size_t)z * BB * HOUT + idx);
        sg.x += v.x; sg.y += v.y; sg.z += v.z; sg.w += v.w;
    }
    float4 sl = *(const float4*)(part3 + idx);
    #pragma unroll
    for (int z = 1; z < S3; z++) {
        float4 v = *(const float4*)(part3 + (size_t)z * BB * HOUT + idx);
        sl.x += v.x; sl.y += v.y; sl.z += v.z; sl.w += v.w;
    }
    float4 g3 = *(const float4*)(b3 + n);
    float4 g4 = *(const float4*)(b4 + n);
    float4 o;
    o.x = fmaxf(sg.x + g3.x, 0.0f) + fmaxf(sl.x + g4.x, 0.0f);
    o.y = fmaxf(sg.y + g3.y, 0.0f) + fmaxf(sl.y + g4.y, 0.0f);
    o.z = fmaxf(sg.z + g3.z, 0.0f) + fmaxf(sl.z + g4.z, 0.0f);
    o.w = fmaxf(sg.w + g3.w, 0.0f) + fmaxf(sl.w + g4.w, 0.0f);
    *(float4*)(out + idx) = o;
}

// ---------------- launch ----------------------------------------------------
extern "C" void kernel_launch(void* const* d_in, const int* in_sizes, int n_in,
                              void* d_out, int out_size) {
    const float* images    = (const float*)d_in[0];
    const float* locations = (const float*)d_in[1];
    const float* W1        = (const float*)d_in[2];
    const float* b1        = (const float*)d_in[3];
    const float* W2        = (const float*)d_in[4];
    const float* b2        = (const float*)d_in[5];
    const float* W3        = (const float*)d_in[6];
    const float* b3        = (const float*)d_in[7];
    const float* W4        = (const float*)d_in[8];
    const float* b4        = (const float*)d_in[9];
    float* out = (float*)d_out;
    (void)in_sizes; (void)n_in; (void)out_size;

    void *p1p, *p2p, *p3p;
    void *ghp, *glp, *h1hp, *h1lp, *h2hp, *h2lp;
    void *w1hp, *w1lp, *w3hp, *w3lp, *w4hp, *w4lp;
    cudaGetSymbolAddress(&p1p,  part1);
    cudaGetSymbolAddress(&p2p,  part2);
    cudaGetSymbolAddress(&p3p,  part3);
    cudaGetSymbolAddress(&ghp,  g_h);  cudaGetSymbolAddress(&glp,  g_l);
    cudaGetSymbolAddress(&h1hp, h1_h); cudaGetSymbolAddress(&h1lp, h1_l);
    cudaGetSymbolAddress(&h2hp, h2_h); cudaGetSymbolAddress(&h2lp, h2_l);
    cudaGetSymbolAddress(&w1hp, w1_h); cudaGetSymbolAddress(&w1lp, w1_l);
    cudaGetSymbolAddress(&w3hp, w3_h); cudaGetSymbolAddress(&w3lp, w3_l);
    cudaGetSymbolAddress(&w4hp, w4_h); cudaGetSymbolAddress(&w4lp, w4_l);

    // 1) all W splits (one launch)
    conv_all_kernel<<<(CONV_TOT + 255) / 256, 256>>>(W1, W3, W4);

    // 2) foveation + location FC (one launch; LOC_BLOCKS = BB/2 = 128)
    fov_loc_kernel<<<FOV_BLOCKS + LOC_BLOCKS, 256>>>(images, locations, W2, b2);

    // 3) hl partials: h2 @ W4  (M=256, N=1280, K=256, S=2)
    mma_gemm_kernel<<<dim3(HOUT / 64, BB / 64, S3), 128>>>(
        (const __nv_bfloat16*)h2hp, (const __nv_bfloat16*)h2lp,
        (const __nv_bfloat16*)w4hp, (const __nv_bfloat16*)w4lp,
        (float*)p3p, BB, HOUT, HLN, HLN / S3);

    // 4) GEMM1 partials: g @ W1 (M=256, N=1024, K=9216, S=9)  [ncu window]
    mma_gemm_kernel<<<dim3(HGN / 64, BB / 64, S1), 128>>>(
        (const __nv_bfloat16*)ghp, (const __nv_bfloat16*)glp,
        (const __nv_bfloat16*)w1hp, (const __nv_bfloat16*)w1lp,
        (float*)p1p, BB, HGN, GDIM, GDIM / S1);

    // 5) h1 = relu(sum part1 + b1) -> bf16 hi/lo directly
    reduce1_kernel<<<(BB * HGN / 4 + 255) / 256, 256>>>(b1);

    // 6) out partials: h1 @ W3 (M=256, N=1280, K=1024, S=4)
    mma_gemm_kernel<<<dim3(HOUT / 64, BB / 64, S2), 128>>>(
        (const __nv_bfloat16*)h1hp, (const __nv_bfloat16*)h1lp,
        (const __nv_bfloat16*)w3hp, (const __nv_bfloat16*)w3lp,
        (float*)p2p, BB, HOUT, HGN, HGN / S2);

    // 7) out = relu(sum part2 + b3) + relu(sum part3 + b4)
    final_reduce_kernel<<<(BB * HOUT / 4 + 255) / 256, 256>>>(b3, b4, out);
}